// round 1
// baseline (speedup 1.0000x reference)
#include <cuda_runtime.h>

#define BATCH 16
#define HH 256
#define WW 256
#define CCH 16
#define HIDN 128
#define NPIX (BATCH*HH*WW)

// Scratch (allocation-free rule: __device__ globals)
__device__ float g_xnew[(size_t)NPIX * CCH];   // 64MB
__device__ float g_aold[NPIX];                 // 4MB
__device__ float g_anew[NPIX];                 // 4MB

// ---------------- Pass 1 ----------------
// One CTA = 128 pixels of one row (tile). 256 threads.
// SMEM layout (floats):
//   YS   [48][128]   off 0      (6144)
//   W1S  [48][128]   off 6144   (6144)
//   XH   [48][132]   off 12288  (6336)   (3 halo rows x 16 ch, channel-major, 132-col pad)
//   HS   [128][129]  off 12288  (16512)  (overlaps XH; XH dead before HS written)
//   W2S  [128][16]   off 28800  (2048)
// total = 30848 floats = 123392 bytes
#define SMEM_FLOATS 30848
#define SMEM_BYTES  123392

extern __shared__ float sm1[];

__global__ void __launch_bounds__(256, 1) nca_pass1(
    const float* __restrict__ x, const float* __restrict__ W1,
    const float* __restrict__ b1, const float* __restrict__ W2,
    const float* __restrict__ b2, const float* __restrict__ ru)
{
    float* YS  = sm1;
    float* W1S = sm1 + 6144;
    float* XH  = sm1 + 12288;
    float* HS  = sm1 + 12288;   // overlaps XH (safe: see sync ordering)
    float* W2S = sm1 + 28800;

    const int t    = threadIdx.x;
    const int bid  = blockIdx.x;
    const int tile = bid & 1;
    const int row  = bid >> 1;
    const int b    = row >> 8;
    const int i    = row & 255;
    const int j0   = tile << 7;

    // --- cooperative loads: W1, W2, x-halo ---
    for (int q = t; q < 1536; q += 256)
        ((float4*)W1S)[q] = ((const float4*)W1)[q];
    for (int q = t; q < 512; q += 256)
        ((float4*)W2S)[q] = ((const float4*)W2)[q];

    // x-halo: 3 rows x 130 cols x 16 ch, transposed to channel-major in SMEM.
    // 1560 float4 gmem loads (coalesced), 4 scattered STS each.
    for (int task = t; task < 1560; task += 256) {
        int rr  = task / 520;
        int rem = task - rr * 520;
        int cc  = rem >> 2;
        int cg  = rem & 3;
        int gi  = i + rr - 1;
        int jc  = j0 + cc - 1;
        float4 v = make_float4(0.f, 0.f, 0.f, 0.f);
        if (gi >= 0 && gi < HH && jc >= 0 && jc < WW) {
            v = *(const float4*)(x + (((size_t)(b * HH + gi) * WW + jc) << 4) + (cg << 2));
        }
        float* dst = XH + (rr * 16 + (cg << 2)) * 132 + cc;
        dst[0]   = v.x;
        dst[132] = v.y;
        dst[264] = v.z;
        dst[396] = v.w;
    }
    __syncthreads();

    const int p = t & 127;   // pixel within tile (epilogue mapping)
    const int g = t >> 7;    // channel half (epilogue mapping)

    // stash old x (channels g*8..g*8+7 of pixel p) before XH gets overwritten by HS
    float xold[8];
    #pragma unroll
    for (int c8 = 0; c8 < 8; c8++)
        xold[c8] = XH[(16 + g * 8 + c8) * 132 + 1 + p];

    // --- perceive: y[3c]=ident, y[3c+1]=sobel_x, y[3c+2]=sobel_y ---
    for (int task = t; task < 2048; task += 256) {
        int pp = task & 127;
        int c  = task >> 7;
        const float* r0 = XH + (c)      * 132 + pp;
        const float* r1 = XH + (16 + c) * 132 + pp;
        const float* r2 = XH + (32 + c) * 132 + pp;
        float a00 = r0[0], a01 = r0[1], a02 = r0[2];
        float a10 = r1[0], a11 = r1[1], a12 = r1[2];
        float a20 = r2[0], a21 = r2[1], a22 = r2[2];
        float ydx = ((a02 + 2.f * a12 + a22) - (a00 + 2.f * a10 + a20)) * 0.125f;
        float ydy = ((a20 + 2.f * a21 + a22) - (a00 + 2.f * a01 + a02)) * 0.125f;
        YS[(3 * c + 0) * 128 + pp] = a11;
        YS[(3 * c + 1) * 128 + pp] = ydx;
        YS[(3 * c + 2) * 128 + pp] = ydy;
    }
    __syncthreads();

    // --- GEMM1: H[128px][128hid] = relu(Y[128][48] @ W1[48][128] + b1) ---
    // thread (tx,ty): tx = hid block (hids tx*4+{0..3} and 64+tx*4+{0..3}), ty = pixel block (8 px)
    const int tx = t & 15;
    const int ty = t >> 4;

    float bb[8];
    #pragma unroll
    for (int jj = 0; jj < 8; jj++)
        bb[jj] = b1[tx * 4 + (jj & 3) + ((jj >> 2) << 6)];

    float acc[8][8];
    #pragma unroll
    for (int ii = 0; ii < 8; ii++)
        #pragma unroll
        for (int jj = 0; jj < 8; jj++)
            acc[ii][jj] = 0.f;

    #pragma unroll 4
    for (int k = 0; k < 48; k++) {
        float4 a0 = *(float4*)(YS + k * 128 + ty * 8);
        float4 a1 = *(float4*)(YS + k * 128 + ty * 8 + 4);
        float4 w0 = *(float4*)(W1S + k * 128 + tx * 4);
        float4 w1 = *(float4*)(W1S + k * 128 + 64 + tx * 4);
        float av[8] = {a0.x, a0.y, a0.z, a0.w, a1.x, a1.y, a1.z, a1.w};
        float wv[8] = {w0.x, w0.y, w0.z, w0.w, w1.x, w1.y, w1.z, w1.w};
        #pragma unroll
        for (int ii = 0; ii < 8; ii++)
            #pragma unroll
            for (int jj = 0; jj < 8; jj++)
                acc[ii][jj] += av[ii] * wv[jj];
    }

    // relu + bias -> HS (stride 129: GEMM2 row reads conflict-free)
    #pragma unroll
    for (int ii = 0; ii < 8; ii++) {
        int pr = ty * 8 + ii;
        #pragma unroll
        for (int jj = 0; jj < 8; jj++) {
            int hd = tx * 4 + (jj & 3) + ((jj >> 2) << 6);
            HS[pr * 129 + hd] = fmaxf(acc[ii][jj] + bb[jj], 0.f);
        }
    }
    __syncthreads();

    // --- GEMM2: dx[128px][16] = H @ W2 + b2; fused stochastic update ---
    float b2v[8];
    #pragma unroll
    for (int c = 0; c < 8; c++) b2v[c] = b2[g * 8 + c];

    float acc2[8] = {0.f, 0.f, 0.f, 0.f, 0.f, 0.f, 0.f, 0.f};
    #pragma unroll 4
    for (int d = 0; d < 128; d++) {
        float hv = HS[p * 129 + d];
        float4 w0 = *(float4*)(W2S + d * 16 + g * 8);
        float4 w1 = *(float4*)(W2S + d * 16 + g * 8 + 4);
        acc2[0] += hv * w0.x; acc2[1] += hv * w0.y;
        acc2[2] += hv * w0.z; acc2[3] += hv * w0.w;
        acc2[4] += hv * w1.x; acc2[5] += hv * w1.y;
        acc2[6] += hv * w1.z; acc2[7] += hv * w1.w;
    }

    size_t pix = (size_t)(b * HH + i) * WW + j0 + p;
    float u  = ru[pix];
    float um = (u <= 0.5f) ? 1.f : 0.f;   // FIRE_RATE = 0.5, STEP_SIZE = 1.0
    float xn[8];
    #pragma unroll
    for (int c = 0; c < 8; c++)
        xn[c] = xold[c] + (acc2[c] + b2v[c]) * um;

    float4* dst = (float4*)(g_xnew + pix * 16 + g * 8);
    dst[0] = make_float4(xn[0], xn[1], xn[2], xn[3]);
    dst[1] = make_float4(xn[4], xn[5], xn[6], xn[7]);
    if (g == 0) {                    // alpha = channel 3 (lives in half g=0)
        g_aold[pix] = xold[3];
        g_anew[pix] = xn[3];
    }
}

// ---------------- Pass 2 ----------------
// One CTA per image row (W=256 = blockDim). 3x3 maxpool (SAME, -inf pad) on
// old/new alpha; out = x_new * (pre & post).
__global__ void __launch_bounds__(256) nca_pass2(float* __restrict__ out)
{
    __shared__ float sao[3][256];
    __shared__ float san[3][256];
    const int t   = threadIdx.x;
    const int row = blockIdx.x;
    const int b   = row >> 8;
    const int i   = row & 255;

    #pragma unroll
    for (int rr = 0; rr < 3; rr++) {
        int gi = i + rr - 1;
        float vo = -1e30f, vn = -1e30f;
        if (gi >= 0 && gi < HH) {
            size_t idx = (size_t)(b * HH + gi) * WW + t;
            vo = g_aold[idx];
            vn = g_anew[idx];
        }
        sao[rr][t] = vo;
        san[rr][t] = vn;
    }
    __syncthreads();

    float mo = -1e30f, mn = -1e30f;
    #pragma unroll
    for (int rr = 0; rr < 3; rr++) {
        #pragma unroll
        for (int dc = 0; dc < 3; dc++) {
            int jc = t + dc - 1;
            if (jc >= 0 && jc < WW) {
                mo = fmaxf(mo, sao[rr][jc]);
                mn = fmaxf(mn, san[rr][jc]);
            }
        }
    }
    float mask = (mo > 0.1f && mn > 0.1f) ? 1.f : 0.f;

    size_t pix = (size_t)row * WW + t;
    const float4* src = (const float4*)(g_xnew + pix * 16);
    float4*       dst = (float4*)(out + pix * 16);
    #pragma unroll
    for (int q = 0; q < 4; q++) {
        float4 v = src[q];
        v.x *= mask; v.y *= mask; v.z *= mask; v.w *= mask;
        dst[q] = v;
    }
}

extern "C" void kernel_launch(void* const* d_in, const int* in_sizes, int n_in,
                              void* d_out, int out_size)
{
    // Defensive input matching by element count (all sizes unique):
    // x=16777216, W1=6144, b1=128, W2=2048, b2=16, rand_u=1048576
    const float *x = nullptr, *W1 = nullptr, *b1 = nullptr,
                *W2 = nullptr, *b2 = nullptr, *ru = nullptr;
    for (int k = 0; k < n_in; k++) {
        switch (in_sizes[k]) {
            case 16777216: x  = (const float*)d_in[k]; break;
            case 6144:     W1 = (const float*)d_in[k]; break;
            case 128:      b1 = (const float*)d_in[k]; break;
            case 2048:     W2 = (const float*)d_in[k]; break;
            case 16:       b2 = (const float*)d_in[k]; break;
            case 1048576:  ru = (const float*)d_in[k]; break;
            default: break;
        }
    }
    float* out = (float*)d_out;

    cudaFuncSetAttribute(nca_pass1, cudaFuncAttributeMaxDynamicSharedMemorySize, SMEM_BYTES);
    nca_pass1<<<8192, 256, SMEM_BYTES>>>(x, W1, b1, W2, b2, ru);
    nca_pass2<<<4096, 256>>>(out);
}

// round 3
// speedup vs baseline: 1.6101x; 1.6101x over previous
#include <cuda_runtime.h>
#include <cuda_bf16.h>
#include <cstdint>

#define BATCH 16
#define HH 256
#define WW 256
#define NPIX (BATCH*HH*WW)

// ---- scratch (__device__ globals; no allocs allowed) ----
__device__ float g_xnew[(size_t)NPIX * 16];   // 64MB
__device__ float g_aold[NPIX];                // 4MB
__device__ float g_anew[NPIX];                // 4MB
// pre-swizzled weight tile images (padded row strides, bf16)
__device__ __align__(16) unsigned char g_B1[128 * 152 * 2];  // [128n][152k] (144 used)
__device__ __align__(16) unsigned char g_B2[16 * 392 * 2];   // [16n][392k]  (384 used)

// ================= warp-MMA helpers (sm_80+ ISA, valid on compute_103) =====
__device__ __forceinline__ uint32_t smem_u32(const void* p) {
    uint32_t a;
    asm("{ .reg .u64 t; cvta.to.shared.u64 t, %1; cvt.u32.u64 %0, t; }" : "=r"(a) : "l"(p));
    return a;
}

__device__ __forceinline__ void ldsm4(uint32_t* r, uint32_t addr) {
    asm volatile("ldmatrix.sync.aligned.m8n8.x4.shared.b16 {%0,%1,%2,%3}, [%4];"
        : "=r"(r[0]), "=r"(r[1]), "=r"(r[2]), "=r"(r[3]) : "r"(addr));
}

__device__ __forceinline__ void mma_bf16(float* d, const uint32_t* a, uint32_t b0, uint32_t b1) {
    asm volatile("mma.sync.aligned.m16n8k16.row.col.f32.bf16.bf16.f32 "
        "{%0,%1,%2,%3}, {%4,%5,%6,%7}, {%8,%9}, {%0,%1,%2,%3};"
        : "+f"(d[0]), "+f"(d[1]), "+f"(d[2]), "+f"(d[3])
        : "r"(a[0]), "r"(a[1]), "r"(a[2]), "r"(a[3]), "r"(b0), "r"(b1));
}

__device__ __forceinline__ uint16_t bf16_bits(float f) {
    return __bfloat16_as_ushort(__float2bfloat16(f));
}
__device__ __forceinline__ float bf16_val(uint16_t u) {
    return __bfloat162float(__ushort_as_bfloat16(u));
}

// ================= prep: build padded bf16 hi/lo weight tiles ==============
// B1[n][k]: k 0:48 = W1hi[k][n], 48:96 = W1hi[k][n], 96:144 = W1lo[k][n]
//   (pairs with A1 = [Yhi | Ylo | Yhi]:  Yhi*Whi + Ylo*Whi + Yhi*Wlo)
// B2[c][k]: k 0:128 = W2hi[d][c], 128:256 = W2hi, 256:384 = W2lo
__global__ void nca_prep(const float* __restrict__ W1, const float* __restrict__ W2)
{
    int t = threadIdx.x;
    uint32_t* z1 = (uint32_t*)g_B1;
    uint32_t* z2 = (uint32_t*)g_B2;
    for (int q = t; q < 128 * 152 / 2; q += 256) z1[q] = 0;
    for (int q = t; q < 16 * 392 / 2;  q += 256) z2[q] = 0;
    __syncthreads();

    __nv_bfloat16* B1 = (__nv_bfloat16*)g_B1;
    __nv_bfloat16* B2 = (__nv_bfloat16*)g_B2;
    for (int q = t; q < 6144; q += 256) {          // W1 [48k][128n]
        int k = q >> 7, n = q & 127;
        float v = W1[q];
        __nv_bfloat16 h = __float2bfloat16(v);
        float r = v - __bfloat162float(h);
        B1[n * 152 + k]      = h;
        B1[n * 152 + 48 + k] = h;
        B1[n * 152 + 96 + k] = __float2bfloat16(r);
    }
    for (int q = t; q < 2048; q += 256) {          // W2 [128d][16c]
        int d = q >> 4, c = q & 15;
        float v = W2[q];
        __nv_bfloat16 h = __float2bfloat16(v);
        float r = v - __bfloat162float(h);
        B2[c * 392 + d]       = h;
        B2[c * 392 + 128 + d] = h;
        B2[c * 392 + 256 + d] = __float2bfloat16(r);
    }
}

// Wait — careful with term pairing. A1 = [Yhi(0:48) | Ylo(48:96) | Yhi(96:144)],
// so B1 must be [Whi ; Whi ; Wlo] as written above. The terms are:
// Yhi*Whi + Ylo*Whi + Yhi*Wlo. Correct.

// ================= Pass 1 ===================================================
// CTA = 128 pixels (half row), 256 threads / 8 warps. Warp w owns pixel rows
// [16w, 16w+16).
//
// SMEM (bytes), phase A:  A1 @0 (38912 = 128x152 bf16), B1 @38912 (38912),
//                         XH @77824 (25344 = 48x132 f32)   total 103168
// phase B (overlays):     H  @0 (67584 = 128x264 bf16), B2 @67584 (12544),
//                         b1 @80128 (512), b2 @80640 (64)
#define SM_A1   0
#define SM_B1   38912
#define SM_XH   77824
#define SM_H    0
#define SM_B2   67584
#define SM_B1V  80128
#define SM_B2V  80640
#define SMEM_BYTES 103168

extern __shared__ unsigned char sm[];

__global__ void __launch_bounds__(256, 2) nca_pass1(
    const float* __restrict__ x,  const float* __restrict__ b1,
    const float* __restrict__ b2, const float* __restrict__ ru)
{
    const uint32_t smb = smem_u32(sm);
    float* XH = (float*)(sm + SM_XH);

    const int t    = threadIdx.x;
    const int w    = t >> 5;
    const int lane = t & 31;
    const int bid  = blockIdx.x;
    const int tile = bid & 1;
    const int row  = bid >> 1;
    const int b    = row >> 8;
    const int i    = row & 255;
    const int j0   = tile << 7;

    // ---- phase A loads: B1 tile + x-halo ----
    for (int q = t; q < 2432; q += 256)
        ((float4*)(sm + SM_B1))[q] = ((const float4*)g_B1)[q];

    for (int task = t; task < 1560; task += 256) {
        int rr  = task / 520;
        int rem = task - rr * 520;
        int cc  = rem >> 2;
        int cg  = rem & 3;
        int gi  = i + rr - 1;
        int jc  = j0 + cc - 1;
        float4 v = make_float4(0.f, 0.f, 0.f, 0.f);
        if (gi >= 0 && gi < HH && jc >= 0 && jc < WW)
            v = *(const float4*)(x + (((size_t)(b * HH + gi) * WW + jc) << 4) + (cg << 2));
        float* dst = XH + (rr * 16 + (cg << 2)) * 132 + cc;
        dst[0] = v.x; dst[132] = v.y; dst[264] = v.z; dst[396] = v.w;
    }
    __syncthreads();

    // ---- stash old x for this thread's epilogue pixels/channels ----
    // epilogue2 mapping: p0 = 16w + lane/4, p1 = p0+8; channels c0,c0+1,c0+8,c0+9
    const int p0 = 16 * w + (lane >> 2);
    const int p1 = p0 + 8;
    const int c0 = (lane & 3) * 2;
    float xold[8];
    #pragma unroll
    for (int px = 0; px < 2; px++) {
        int p = px ? p1 : p0;
        xold[px * 4 + 0] = XH[(16 + c0)     * 132 + 1 + p];
        xold[px * 4 + 1] = XH[(16 + c0 + 1) * 132 + 1 + p];
        xold[px * 4 + 2] = XH[(16 + c0 + 8) * 132 + 1 + p];
        xold[px * 4 + 3] = XH[(16 + c0 + 9) * 132 + 1 + p];
    }

    // ---- perceive -> A1 bf16 tile [128px][152] (hi 0:48 | lo 48:96 | hi 96:144)
    __nv_bfloat16* A1 = (__nv_bfloat16*)(sm + SM_A1);
    for (int task = t; task < 2048; task += 256) {
        int pp = task & 127;
        int c  = task >> 7;
        const float* r0 = XH + (c)      * 132 + pp;
        const float* r1 = XH + (16 + c) * 132 + pp;
        const float* r2 = XH + (32 + c) * 132 + pp;
        float a00 = r0[0], a01 = r0[1], a02 = r0[2];
        float a10 = r1[0], a11 = r1[1], a12 = r1[2];
        float a20 = r2[0], a21 = r2[1], a22 = r2[2];
        float yv[3];
        yv[0] = a11;
        yv[1] = ((a02 + 2.f * a12 + a22) - (a00 + 2.f * a10 + a20)) * 0.125f;
        yv[2] = ((a20 + 2.f * a21 + a22) - (a00 + 2.f * a01 + a02)) * 0.125f;
        #pragma unroll
        for (int e = 0; e < 3; e++) {
            int k = 3 * c + e;
            __nv_bfloat16 h = __float2bfloat16(yv[e]);
            float r = yv[e] - __bfloat162float(h);
            A1[pp * 152 + k]      = h;
            A1[pp * 152 + 96 + k] = h;
            A1[pp * 152 + 48 + k] = __float2bfloat16(r);
        }
    }
    __syncthreads();

    // ---- GEMM1: acc[16 n-tiles][4] = A1[16w..][144] x B1[144][128] ----
    float acc[16][4];
    #pragma unroll
    for (int j = 0; j < 16; j++)
        #pragma unroll
        for (int r = 0; r < 4; r++) acc[j][r] = 0.f;

    {
        const uint32_t aRow = smb + SM_A1 + (16 * w + (lane & 15)) * 304 + (lane >> 4) * 16;
        const uint32_t bRow = smb + SM_B1 + ((lane & 7) + ((lane >> 4) & 1) * 8) * 304
                                          + ((lane >> 3) & 1) * 16;
        #pragma unroll
        for (int ks = 0; ks < 9; ks++) {
            uint32_t a[4];
            ldsm4(a, aRow + ks * 32);
            #pragma unroll
            for (int jj = 0; jj < 8; jj++) {
                uint32_t bb[4];
                ldsm4(bb, bRow + jj * (16 * 304) + ks * 32);
                mma_bf16(acc[2 * jj],     a, bb[0], bb[1]);
                mma_bf16(acc[2 * jj + 1], a, bb[2], bb[3]);
            }
        }
    }
    __syncthreads();   // A1/B1/XH dead

    // ---- phase B loads: B2 tile + bias vectors ----
    for (int q = t; q < 784; q += 256)
        ((float4*)(sm + SM_B2))[q] = ((const float4*)g_B2)[q];
    if (t < 128) ((float*)(sm + SM_B1V))[t] = b1[t];
    if (t < 16)  ((float*)(sm + SM_B2V))[t] = b2[t];

    // ---- epilogue1: h = relu(acc + b1) -> H bf16 [128px][264] (hi | lo) ----
    {
        __nv_bfloat16* Ht = (__nv_bfloat16*)(sm + SM_H);
        const float* b1s = (const float*)(sm + SM_B1V);
        // NOTE: b1s read requires the `if (t<128)` store above + membar via
        // syncthreads -- but we also write H into the same region A1 occupied;
        // the preceding __syncthreads() already ordered GEMM1 reads. We need one
        // more sync so b1s is visible before use:
        __syncthreads();
        #pragma unroll
        for (int j = 0; j < 16; j++) {
            int n = 8 * j + c0;
            float bn0 = b1s[n], bn1 = b1s[n + 1];
            #pragma unroll
            for (int r = 0; r < 2; r++) {
                int p = r ? p1 : p0;
                float v0 = fmaxf(acc[j][2 * r]     + bn0, 0.f);
                float v1 = fmaxf(acc[j][2 * r + 1] + bn1, 0.f);
                uint16_t h0 = bf16_bits(v0), h1 = bf16_bits(v1);
                uint16_t l0 = bf16_bits(v0 - bf16_val(h0));
                uint16_t l1 = bf16_bits(v1 - bf16_val(h1));
                *(uint32_t*)(Ht + p * 264 + n)       = (uint32_t)h0 | ((uint32_t)h1 << 16);
                *(uint32_t*)(Ht + p * 264 + 128 + n) = (uint32_t)l0 | ((uint32_t)l1 << 16);
            }
        }
    }
    __syncthreads();

    // ---- GEMM2: acc2[2][4] = H[16w..][K] x B2 ----
    float acc2[2][4];
    #pragma unroll
    for (int j = 0; j < 2; j++)
        #pragma unroll
        for (int r = 0; r < 4; r++) acc2[j][r] = 0.f;

    {
        const uint32_t aRow = smb + SM_H + (16 * w + (lane & 15)) * 528 + (lane >> 4) * 16;
        const uint32_t bRow = smb + SM_B2 + ((lane & 7) + ((lane >> 4) & 1) * 8) * 784
                                          + ((lane >> 3) & 1) * 16;
        #pragma unroll
        for (int ks = 0; ks < 16; ks++) {       // Hhi*W2hi + Hlo*W2hi
            uint32_t a[4], bb[4];
            ldsm4(a,  aRow + ks * 32);
            ldsm4(bb, bRow + ks * 32);
            mma_bf16(acc2[0], a, bb[0], bb[1]);
            mma_bf16(acc2[1], a, bb[2], bb[3]);
        }
        #pragma unroll
        for (int ks = 0; ks < 8; ks++) {        // Hhi*W2lo
            uint32_t a[4], bb[4];
            ldsm4(a,  aRow + ks * 32);
            ldsm4(bb, bRow + 512 + ks * 32);
            mma_bf16(acc2[0], a, bb[0], bb[1]);
            mma_bf16(acc2[1], a, bb[2], bb[3]);
        }
    }

    // ---- epilogue2: dx + stochastic update -> g_xnew / alpha arrays ----
    {
        const float* b2s = (const float*)(sm + SM_B2V);
        float bc0 = b2s[c0], bc1 = b2s[c0 + 1], bc8 = b2s[c0 + 8], bc9 = b2s[c0 + 9];
        #pragma unroll
        for (int px = 0; px < 2; px++) {
            int p = px ? p1 : p0;
            size_t pix = (size_t)(b * HH + i) * WW + j0 + p;
            float um = (ru[pix] <= 0.5f) ? 1.f : 0.f;
            float xn0 = xold[px * 4 + 0] + (acc2[0][2 * px]     + bc0) * um;
            float xn1 = xold[px * 4 + 1] + (acc2[0][2 * px + 1] + bc1) * um;
            float xn2 = xold[px * 4 + 2] + (acc2[1][2 * px]     + bc8) * um;
            float xn3 = xold[px * 4 + 3] + (acc2[1][2 * px + 1] + bc9) * um;
            *(float2*)(g_xnew + pix * 16 + c0)     = make_float2(xn0, xn1);
            *(float2*)(g_xnew + pix * 16 + c0 + 8) = make_float2(xn2, xn3);
            if ((lane & 3) == 1) {                 // c0 == 2 -> channel 3 = slot 1
                g_aold[pix] = xold[px * 4 + 1];
                g_anew[pix] = xn1;
            }
        }
    }
}

// ================= Pass 2 ===================================================
__global__ void __launch_bounds__(256) nca_pass2(float* __restrict__ out)
{
    __shared__ float sao[3][256];
    __shared__ float san[3][256];
    const int t   = threadIdx.x;
    const int row = blockIdx.x;
    const int b   = row >> 8;
    const int i   = row & 255;

    #pragma unroll
    for (int rr = 0; rr < 3; rr++) {
        int gi = i + rr - 1;
        float vo = -1e30f, vn = -1e30f;
        if (gi >= 0 && gi < HH) {
            size_t idx = (size_t)(b * HH + gi) * WW + t;
            vo = g_aold[idx];
            vn = g_anew[idx];
        }
        sao[rr][t] = vo;
        san[rr][t] = vn;
    }
    __syncthreads();

    float mo = -1e30f, mn = -1e30f;
    #pragma unroll
    for (int rr = 0; rr < 3; rr++) {
        #pragma unroll
        for (int dc = 0; dc < 3; dc++) {
            int jc = t + dc - 1;
            if (jc >= 0 && jc < WW) {
                mo = fmaxf(mo, sao[rr][jc]);
                mn = fmaxf(mn, san[rr][jc]);
            }
        }
    }
    float mask = (mo > 0.1f && mn > 0.1f) ? 1.f : 0.f;

    size_t pix = (size_t)row * WW + t;
    const float4* src = (const float4*)(g_xnew + pix * 16);
    float4*       dst = (float4*)(out + pix * 16);
    #pragma unroll
    for (int q = 0; q < 4; q++) {
        float4 v = src[q];
        v.x *= mask; v.y *= mask; v.z *= mask; v.w *= mask;
        dst[q] = v;
    }
}

extern "C" void kernel_launch(void* const* d_in, const int* in_sizes, int n_in,
                              void* d_out, int out_size)
{
    const float *x = nullptr, *W1 = nullptr, *b1 = nullptr,
                *W2 = nullptr, *b2 = nullptr, *ru = nullptr;
    for (int k = 0; k < n_in; k++) {
        switch (in_sizes[k]) {
            case 16777216: x  = (const float*)d_in[k]; break;
            case 6144:     W1 = (const float*)d_in[k]; break;
            case 128:      b1 = (const float*)d_in[k]; break;
            case 2048:     W2 = (const float*)d_in[k]; break;
            case 16:       b2 = (const float*)d_in[k]; break;
            case 1048576:  ru = (const float*)d_in[k]; break;
            default: break;
        }
    }
    float* out = (float*)d_out;

    cudaFuncSetAttribute(nca_pass1, cudaFuncAttributeMaxDynamicSharedMemorySize, SMEM_BYTES);
    nca_prep<<<1, 256>>>(W1, W2);
    nca_pass1<<<8192, 256, SMEM_BYTES>>>(x, b1, b2, ru);
    nca_pass2<<<4096, 256>>>(out);
}